// round 15
// baseline (speedup 1.0000x reference)
#include <cuda_runtime.h>
#include <cuda_bf16.h>
#include <math.h>

static constexpr int Bb = 2, Tt = 2048, Dm = 1024, Hh = 16, Cc = 64;
static constexpr int BT  = Bb * Tt;
static constexpr int NC  = Tt / Cc;
static constexpr long BLK = (long)BT * Dm;

__device__ __align__(256) float g_scratch[18 * 4194304 + 2 * 262144 + 3 * 65536];

static constexpr int R1_SMEM  = (5 * 4160 + 192) * 4;   // 83968 B -> 2 blocks/SM
static constexpr int GEMM_SMEM = 65536;
static constexpr int R2O_SMEM = 4 * 64 * 68 * 4;        // 69632 B
static constexpr int R2S_SMEM = (3 * 4160 + 64) * 4;    // 50176 B

__device__ __forceinline__ unsigned smem_u32(const void* p) {
    return (unsigned)__cvta_generic_to_shared(p);
}
__device__ __forceinline__ void cp16(unsigned dst, const void* src) {
    asm volatile("cp.async.cg.shared.global [%0], [%1], 16;" :: "r"(dst), "l"(src));
}
__device__ __forceinline__ void cp_commit() {
    asm volatile("cp.async.commit_group;" ::: "memory");
}
__device__ __forceinline__ void cp_wait0() {
    asm volatile("cp.async.wait_group 0;" ::: "memory");
}
__device__ __forceinline__ void ldsm4(unsigned* r, unsigned addr) {
    asm volatile("ldmatrix.sync.aligned.m8n8.x4.shared.b16 {%0,%1,%2,%3},[%4];"
        : "=r"(r[0]), "=r"(r[1]), "=r"(r[2]), "=r"(r[3]) : "r"(addr));
}
__device__ __forceinline__ void mma_bf16(float* d, const unsigned* a, unsigned b0, unsigned b1) {
    asm volatile("mma.sync.aligned.m16n8k16.row.col.f32.bf16.bf16.f32 "
        "{%0,%1,%2,%3},{%4,%5,%6,%7},{%8,%9},{%0,%1,%2,%3};"
        : "+f"(d[0]), "+f"(d[1]), "+f"(d[2]), "+f"(d[3])
        : "r"(a[0]), "r"(a[1]), "r"(a[2]), "r"(a[3]), "r"(b0), "r"(b1));
}
__device__ __forceinline__ void bf16_split_store(__nv_bfloat16* dst, size_t idx, float v) {
    __nv_bfloat16 h = __float2bfloat16(v);
    float lo = v - __bfloat162float(h);
    dst[idx] = h;
    dst[idx + 32] = __float2bfloat16(lo);
}

// ---- LAUNCH 0: conv+SiLU + weight convert ----
__global__ void __launch_bounds__(256) prep_kernel(
    const float* __restrict__ x,
    const float* __restrict__ wq, const float* __restrict__ bq,
    const float* __restrict__ wk, const float* __restrict__ bk,
    const float* __restrict__ wv, const float* __restrict__ bv,
    const float* __restrict__ Wq, const float* __restrict__ Wk,
    const float* __restrict__ Wv, const float* __restrict__ Wo,
    __nv_bfloat16* __restrict__ xq, __nv_bfloat16* __restrict__ xk,
    __nv_bfloat16* __restrict__ xv, __nv_bfloat16* __restrict__ Wc)
{
    if (blockIdx.x < 49152) {
        long idx = (long)blockIdx.x * 256 + threadIdx.x;
        int d = (int)(idx & (Dm - 1));
        int t = (int)((idx >> 10) & (Tt - 1));
        int b = (int)((idx >> 21) & 1);
        int s = (int)(idx >> 22);
        const float* w  = (s == 0) ? wq : (s == 1) ? wk : wv;
        const float* bi = (s == 0) ? bq : (s == 1) ? bk : bv;
        __nv_bfloat16* o = (s == 0) ? xq : (s == 1) ? xk : xv;
        float acc = bi[d];
        #pragma unroll
        for (int j = 0; j < 4; j++) {
            int tt = t - 3 + j;
            if (tt >= 0) acc += x[((long)b * Tt + tt) * Dm + d] * w[d * 4 + j];
        }
        float sg = 1.0f / (1.0f + __expf(-acc));
        size_t m = (size_t)b * Tt + t;
        bf16_split_store(o, (m * 32 + (d >> 5)) * 64 + (d & 31), acc * sg);
    } else {
        long idx = (long)(blockIdx.x - 49152) * 256 + threadIdx.x;
        int mid = (int)(idx >> 20);
        int r = (int)((idx >> 10) & 1023), k = (int)(idx & 1023);
        const float* src = (mid == 0) ? Wq : (mid == 1) ? Wk : (mid == 2) ? Wv : Wo;
        float a = src[(size_t)r * 1024 + k];
        bf16_split_store(Wc + (size_t)mid * 2097152,
                         ((size_t)r * 32 + (k >> 5)) * 64 + (k & 31), a);
    }
}

// ---- LAUNCH 1: gate down-projections ----
__global__ void __launch_bounds__(256) gates1_kernel(
    const float* __restrict__ x,
    const float* __restrict__ Wad, const float* __restrict__ bad,
    const float* __restrict__ Wgd, const float* __restrict__ bgd,
    const float* __restrict__ Wbe, const float* __restrict__ bbe,
    float* __restrict__ t1, float* __restrict__ t2, float* __restrict__ be)
{
    __shared__ float As[16][65];
    __shared__ float Ws[64][65];
    int bid = blockIdx.x, tid = threadIdx.x;
    int sel = bid >> 8;
    int m0 = (bid & 255) * 16;
    if (sel < 2) {
        const float* W  = sel ? Wgd : Wad;
        const float* bi = sel ? bgd : bad;
        float* outp     = sel ? t2 : t1;
        int col = tid & 63, rg = tid >> 6;
        float acc[4] = {0.f, 0.f, 0.f, 0.f};
        for (int k0 = 0; k0 < 1024; k0 += 64) {
            for (int i = tid; i < 1024; i += 256)
                As[i >> 6][i & 63] = x[(size_t)(m0 + (i >> 6)) * 1024 + k0 + (i & 63)];
            for (int i = tid; i < 4096; i += 256)
                Ws[i >> 6][i & 63] = W[(size_t)(i >> 6) * 1024 + k0 + (i & 63)];
            __syncthreads();
            for (int kk = 0; kk < 64; kk++) {
                float w = Ws[col][kk];
                acc[0] += As[rg][kk] * w;      acc[1] += As[rg + 4][kk] * w;
                acc[2] += As[rg + 8][kk] * w;  acc[3] += As[rg + 12][kk] * w;
            }
            __syncthreads();
        }
        #pragma unroll
        for (int i = 0; i < 4; i++) {
            float v = acc[i] + bi[col];
            v = v / (1.0f + __expf(-v));
            outp[(size_t)(m0 + rg + i * 4) * 64 + col] = v;
        }
    } else {
        int col = tid & 15, rg = tid >> 4;
        float acc = 0.f;
        for (int k0 = 0; k0 < 1024; k0 += 64) {
            for (int i = tid; i < 1024; i += 256)
                As[i >> 6][i & 63] = x[(size_t)(m0 + (i >> 6)) * 1024 + k0 + (i & 63)];
            for (int i = tid; i < 1024; i += 256)
                Ws[i >> 6][i & 63] = Wbe[(size_t)(i >> 6) * 1024 + k0 + (i & 63)];
            __syncthreads();
            for (int kk = 0; kk < 64; kk++) acc += As[rg][kk] * Ws[col][kk];
            __syncthreads();
        }
        float v = acc + bbe[col];
        float s = 1.0f / (1.0f + __expf(-v));
        be[(size_t)(m0 + rg) * 16 + col] = fminf(s, 1.0f);
    }
}

// ---- LAUNCH 2: merged alpha up-proj + output gate up-proj ----
__global__ void __launch_bounds__(256) alphagate_kernel(
    const float* __restrict__ t1, const float* __restrict__ Wau,
    const float* __restrict__ bau, float* __restrict__ al,
    const float* __restrict__ t2, const float* __restrict__ Wgu,
    const float* __restrict__ bgu, float* __restrict__ ga)
{
    int tid = threadIdx.x;
    if (blockIdx.x < 1024) {
        __shared__ float As[16][68];
        __shared__ float Ws[16][68];
        int m0 = (blockIdx.x >> 4) * 64, n0 = (blockIdx.x & 15) * 64;
        int lr = tid >> 2, lk = (tid & 3) * 4;
        int r0 = (tid >> 4) * 4, c0 = (tid & 15) * 4;
        float acc[4][4];
        #pragma unroll
        for (int i = 0; i < 4; i++)
            #pragma unroll
            for (int j = 0; j < 4; j++) acc[i][j] = 0.f;
        for (int k0 = 0; k0 < 64; k0 += 16) {
            float4 av = *(const float4*)&t1[(size_t)(m0 + lr) * 64 + k0 + lk];
            float4 wv = *(const float4*)&Wau[(size_t)(n0 + lr) * 64 + k0 + lk];
            As[lk + 0][lr] = av.x; As[lk + 1][lr] = av.y; As[lk + 2][lr] = av.z; As[lk + 3][lr] = av.w;
            Ws[lk + 0][lr] = wv.x; Ws[lk + 1][lr] = wv.y; Ws[lk + 2][lr] = wv.z; Ws[lk + 3][lr] = wv.w;
            __syncthreads();
            #pragma unroll
            for (int kk = 0; kk < 16; kk++) {
                float4 a4 = *(const float4*)&As[kk][r0];
                float4 w4 = *(const float4*)&Ws[kk][c0];
                float aa[4] = {a4.x, a4.y, a4.z, a4.w};
                float ww[4] = {w4.x, w4.y, w4.z, w4.w};
                #pragma unroll
                for (int i = 0; i < 4; i++)
                    #pragma unroll
                    for (int j = 0; j < 4; j++) acc[i][j] += aa[i] * ww[j];
            }
            __syncthreads();
        }
        #pragma unroll
        for (int i = 0; i < 4; i++) {
            int m = m0 + r0 + i;
            #pragma unroll
            for (int j = 0; j < 4; j++) {
                int nn = n0 + c0 + j;
                float v = acc[i][j] + bau[nn];
                float s = 1.0f / (1.0f + __expf(-v));
                v = fminf(fmaxf(s, 0.1f), 1.0f);
                int b = m >> 11, t = m & 2047;
                int h = nn >> 6, d = nn & 63;
                al[(((size_t)b * Hh + h) * Tt + t) * 64 + d] = v;
            }
        }
    } else {
        __shared__ float As2[16][65];
        __shared__ float Ws2[16][65];
        int m0 = (blockIdx.x - 1024) * 16;
        int col = tid & 15, rg = tid >> 4;
        float acc = 0.f;
        for (int i = tid; i < 1024; i += 256)
            As2[i >> 6][i & 63] = t2[(size_t)(m0 + (i >> 6)) * 64 + (i & 63)];
        for (int i = tid; i < 1024; i += 256)
            Ws2[i >> 6][i & 63] = Wgu[(size_t)(i >> 6) * 64 + (i & 63)];
        __syncthreads();
        for (int kk = 0; kk < 64; kk++) acc += As2[rg][kk] * Ws2[col][kk];
        float v = acc + bgu[col];
        float s = 1.0f / (1.0f + __expf(-v));
        ga[(size_t)(m0 + rg) * 16 + col] = fminf(s, 1.0f);
    }
}

// ---- LAUNCH 3 (PROFILED): big tensor-core GEMM, 2 CTAs/SM ----
template<int MODE>
__global__ void __launch_bounds__(256, 2) gemm_big(
    const __nv_bfloat16* __restrict__ A0, const __nv_bfloat16* __restrict__ A1,
    const __nv_bfloat16* __restrict__ A2, const __nv_bfloat16* __restrict__ Wbase,
    const float* __restrict__ b0, const float* __restrict__ b1,
    const float* __restrict__ b2,
    float* __restrict__ C0, float* __restrict__ C1, float* __restrict__ C2)
{
    extern __shared__ __align__(16) char dynsm[];
    unsigned sbase = smem_u32(dynsm);
    int z = MODE ? blockIdx.z : 3;
    const __nv_bfloat16* A = (z == 0 || z == 3) ? A0 : (z == 1) ? A1 : A2;
    const __nv_bfloat16* W2 = Wbase + (size_t)z * 2097152;
    const float* bias = (z == 0 || z == 3) ? b0 : (z == 1) ? b1 : b2;
    float* C = (z == 0 || z == 3) ? C0 : (z == 1) ? C1 : C2;

    int tid = threadIdx.x;
    int lane = tid & 31, warp = tid >> 5;
    int wn = warp & 1, wm = warp >> 1;
    int m0 = blockIdx.y * 128, n0 = blockIdx.x * 128;
    const int NKC = 32;

    float acc[2][8][4];
    #pragma unroll
    for (int a = 0; a < 2; a++)
        #pragma unroll
        for (int b = 0; b < 8; b++)
            #pragma unroll
            for (int c = 0; c < 4; c++) acc[a][b][c] = 0.f;

    auto load_stage = [&](int s, int c) {
        unsigned abase = sbase + s * 32768;
        unsigned wbase = abase + 16384;
        #pragma unroll
        for (int i = tid; i < 1024; i += 256) {
            int row = i >> 3, q = i & 7;
            unsigned off = row * 128 + ((q ^ (row & 7)) << 4);
            cp16(abase + off, A + ((size_t)(m0 + row) * NKC + c) * 64 + q * 8);
            cp16(wbase + off, W2 + ((size_t)(n0 + row) * NKC + c) * 64 + q * 8);
        }
        cp_commit();
    };

    load_stage(0, 0);
    int cur = 0;
    for (int c = 0; c < NKC; c++) {
        cp_wait0();
        __syncthreads();
        if (c + 1 < NKC) load_stage(cur ^ 1, c + 1);
        unsigned as = sbase + cur * 32768;
        unsigned ws = as + 16384;
        #pragma unroll
        for (int kk = 0; kk < 2; kk++) {
            unsigned a_h[2][4], a_l[2][4];
            #pragma unroll
            for (int mt = 0; mt < 2; mt++) {
                int row = wm * 32 + mt * 16 + (lane & 15);
                int chB = kk * 2 + (lane >> 4);
                ldsm4(a_h[mt], as + row * 128 + ((chB ^ (row & 7)) << 4));
                ldsm4(a_l[mt], as + row * 128 + (((chB + 4) ^ (row & 7)) << 4));
            }
            unsigned b_h[4][4], b_l[4][4];
            #pragma unroll
            for (int nt4 = 0; nt4 < 4; nt4++) {
                int row = wn * 64 + nt4 * 16 + (lane & 15);
                int chB = kk * 2 + (lane >> 4);
                ldsm4(b_h[nt4], ws + row * 128 + ((chB ^ (row & 7)) << 4));
                ldsm4(b_l[nt4], ws + row * 128 + (((chB + 4) ^ (row & 7)) << 4));
            }
            #pragma unroll
            for (int mt = 0; mt < 2; mt++)
                #pragma unroll
                for (int nt = 0; nt < 8; nt++) {
                    int q = nt >> 1, h = nt & 1;
                    mma_bf16(acc[mt][nt], a_h[mt], b_h[q][h], b_h[q][h + 2]);
                    mma_bf16(acc[mt][nt], a_h[mt], b_l[q][h], b_l[q][h + 2]);
                    mma_bf16(acc[mt][nt], a_l[mt], b_h[q][h], b_h[q][h + 2]);
                }
        }
        cur ^= 1;
    }

    int g = lane >> 2, tc = (lane & 3) * 2;
    #pragma unroll
    for (int mt = 0; mt < 2; mt++) {
        #pragma unroll
        for (int nt = 0; nt < 8; nt++)
            #pragma unroll
            for (int q = 0; q < 2; q++) {
                float bv = bias[n0 + wn * 64 + nt * 8 + tc + q];
                acc[mt][nt][q] += bv;
                acc[mt][nt][2 + q] += bv;
            }
        if (MODE && z < 2) {
            #pragma unroll
            for (int p = 0; p < 2; p++) {
                float s = 0.f;
                #pragma unroll
                for (int nt = 0; nt < 8; nt++)
                    #pragma unroll
                    for (int q = 0; q < 2; q++) {
                        float v = acc[mt][nt][p * 2 + q];
                        s += v * v;
                    }
                s += __shfl_xor_sync(0xffffffffu, s, 1);
                s += __shfl_xor_sync(0xffffffffu, s, 2);
                float inv = rsqrtf(fmaxf(s, 1e-6f));
                #pragma unroll
                for (int nt = 0; nt < 8; nt++)
                    #pragma unroll
                    for (int q = 0; q < 2; q++)
                        acc[mt][nt][p * 2 + q] *= inv;
            }
        }
        #pragma unroll
        for (int nt = 0; nt < 8; nt++)
            #pragma unroll
            for (int p = 0; p < 2; p++)
                #pragma unroll
                for (int q = 0; q < 2; q++) {
                    int row = m0 + wm * 32 + mt * 16 + g + p * 8;
                    int col = n0 + wn * 64 + nt * 8 + tc + q;
                    float v = acc[mt][nt][p * 2 + q];
                    if (MODE) {
                        int b = row >> 11, t = row & 2047;
                        int h = col >> 6, d = col & 63;
                        C[(((size_t)b * Hh + h) * Tt + t) * 64 + d] = v;
                    } else {
                        C[(size_t)row * 1024 + col] = v;
                    }
                }
    }
}

// ---- LAUNCH 4: R1 (liveness-overlapped smem) ----
__global__ void __launch_bounds__(256) r1_kernel(
    const float* __restrict__ Q, const float* __restrict__ K,
    const float* __restrict__ V, const float* __restrict__ AL,
    const float* __restrict__ BETA,
    float* __restrict__ Ao, float* __restrict__ Wo_, float* __restrict__ T1o,
    float* __restrict__ Kto, float* __restrict__ lamo)
{
    extern __shared__ float sm[];
    float* cl = sm;
    float* pA = sm + 4160;
    float* Us = sm;
    float* pB = sm + 2 * 4160;
    float* pC = sm + 3 * 4160;
    float* Ms = sm + 4 * 4160;
    float* bs = sm + 5 * 4160;
    float* Em = bs + 64;
    float* E63 = Em + 64;
    int tid = threadIdx.x;
    int cb = blockIdx.x;
    int n = cb >> 5, bh = cb & 31;
    int b = bh >> 4, h = bh & 15;
    long g0 = ((long)bh * Tt + n * 64) * 64;

    for (int i = tid; i < 4096; i += 256) {
        int t = i >> 6, d = i & 63;
        pA[t * 65 + d] = Q[g0 + i];
        pB[t * 65 + d] = K[g0 + i];
        Ms[t * 65 + d] = AL[g0 + i];
    }
    if (tid < 64) bs[tid] = BETA[((long)b * Tt + n * 64 + tid) * 16 + h];
    __syncthreads();

    if (tid < 64) {
        float c = 0.f;
        for (int t = 0; t < 64; t++) {
            c += __logf(fmaxf(Ms[t * 65 + tid], 1e-7f));
            cl[t * 65 + tid] = c;
        }
        float m = cl[31 * 65 + tid];
        Em[tid]  = __expf(m);
        E63[tid] = __expf(cl[63 * 65 + tid] - m);
    }
    __syncthreads();
    for (int i = tid; i < 4096; i += 256) {
        int t = i >> 6, d = i & 63;
        float m  = cl[31 * 65 + d];
        float e  = __expf(cl[t * 65 + d] - m);
        float ei = __expf(m - cl[t * 65 + d]);
        float q = pA[t * 65 + d], k = pB[t * 65 + d];
        pA[t * 65 + d] = q * e;
        pB[t * 65 + d] = k * e;
        pC[t * 65 + d] = k * bs[t] * ei;
    }
    __syncthreads();

    for (int p = tid; p < 2080; p += 256) {
        int i = (int)((sqrtf(8.f * p + 1.f) - 1.f) * 0.5f);
        while ((i + 1) * (i + 2) / 2 <= p) ++i;
        while (i * (i + 1) / 2 > p) --i;
        int j = p - ((i * (i + 1)) >> 1);
        float accA = 0.f, accM = 0.f;
        const float* ai = pA + i * 65;
        const float* bi = pB + i * 65;
        const float* cj = pC + j * 65;
        #pragma unroll 16
        for (int d = 0; d < 64; d++) {
            float c = cj[d];
            accA += ai[d] * c;
            accM += bi[d] * c;
        }
        Ao[(long)cb * 4096 + i * 64 + j] = accA;
        Ms[i * 65 + j] = accM;
    }
    __syncthreads();

    if (tid < 128) {
        int c = tid;
        int d = c & 63;
        for (int t = 0; t < 64; t++) {
            float acc;
            if (c < 64) acc = V[g0 + t * 64 + d];
            else        acc = pB[t * 65 + d];
            for (int s = 0; s < t; s++) acc -= Ms[t * 65 + s] * Us[s * 128 + c];
            Us[t * 128 + c] = acc;
        }
    }
    __syncthreads();

    for (int i = tid; i < 4096; i += 256) {
        int t = i >> 6, e = i & 63;
        T1o[(long)cb * 4096 + i] = Us[t * 128 + e];
        Wo_[(long)cb * 4096 + i] = Us[t * 128 + 64 + e] * Em[e];
        Kto[(long)cb * 4096 + i] = pC[t * 65 + e] * E63[e];
    }
    if (tid < 64) lamo[(long)cb * 64 + tid] = Em[tid] * E63[tid];
}

// ---- LAUNCH 5: R2S — state scan, ONE block per bh (512 thr, 8 cols/thread) ----
__global__ void __launch_bounds__(512) r2s_kernel(
    const float* __restrict__ Wi, const float* __restrict__ T1i,
    const float* __restrict__ Kti, const float* __restrict__ lami,
    float* __restrict__ Sprev)
{
    extern __shared__ float smS[];
    float* S = smS;                 // 64*65
    float* U = smS + 4160;          // 64*65
    float* L = smS + 2 * 4160;      // 64*65 (W then Kt)
    float* lam = smS + 3 * 4160;    // 64
    int tid = threadIdx.x;
    int bh = blockIdx.x;
    int r = tid & 63, cg = tid >> 6;   // cg 0..7
    int c0 = cg * 8;
    for (int i = tid; i < 4160; i += 512) S[i] = 0.f;
    __syncthreads();                 // FIX: init visible before chunk-0 checkpoint

    float wR[8], tR[8], kR[8];
    {
        long gc = (long)bh * 4096;
        #pragma unroll
        for (int m = 0; m < 8; m++) wR[m] = Wi[gc + tid + m * 512];
        #pragma unroll
        for (int j = 0; j < 8; j++) tR[j] = T1i[gc + r * 64 + c0 + j];
    }

    for (int n = 0; n < NC; n++) {
        long cb = (long)n * 32 + bh;
        long gc = cb * 4096;
        // checkpoint own S cells
        #pragma unroll
        for (int j = 0; j < 8; j++)
            Sprev[gc + r * 64 + c0 + j] = S[r * 65 + c0 + j];

        __syncthreads();                     // prior S-update writes + L reads settled
        #pragma unroll
        for (int m = 0; m < 8; m++) { int i = tid + m * 512; L[(i >> 6) * 65 + (i & 63)] = wR[m]; }
        __syncthreads();
        #pragma unroll
        for (int m = 0; m < 8; m++) kR[m] = Kti[gc + tid + m * 512];
        // U = T1 - W @ S
        {
            float u[8];
            #pragma unroll
            for (int j = 0; j < 8; j++) u[j] = tR[j];
            for (int kk = 0; kk < 64; kk++) {
                float w = L[r * 65 + kk];
                const float* Sr = S + kk * 65 + c0;
                #pragma unroll
                for (int j = 0; j < 8; j++) u[j] -= w * Sr[j];
            }
            #pragma unroll
            for (int j = 0; j < 8; j++) U[r * 65 + c0 + j] = u[j];
        }
        __syncthreads();
        #pragma unroll
        for (int m = 0; m < 8; m++) { int i = tid + m * 512; L[(i >> 6) * 65 + (i & 63)] = kR[m]; }
        if (tid < 64) lam[tid] = lami[cb * 64 + tid];
        __syncthreads();
        if (n + 1 < NC) {
            long gc2 = ((long)(n + 1) * 32 + bh) * 4096;
            #pragma unroll
            for (int m = 0; m < 8; m++) wR[m] = Wi[gc2 + tid + m * 512];
            #pragma unroll
            for (int j = 0; j < 8; j++) tR[j] = T1i[gc2 + r * 64 + c0 + j];
        }
        // S = diag(lam)*S + Kt^T @ U
        {
            float lr_ = lam[r];
            float s[8];
            #pragma unroll
            for (int j = 0; j < 8; j++) s[j] = lr_ * S[r * 65 + c0 + j];
            for (int kk = 0; kk < 64; kk++) {
                float kv = L[kk * 65 + r];
                const float* Ur = U + kk * 65 + c0;
                #pragma unroll
                for (int j = 0; j < 8; j++) s[j] += kv * Ur[j];
            }
            #pragma unroll
            for (int j = 0; j < 8; j++) S[r * 65 + c0 + j] = s[j];
        }
    }
}

// ---- LAUNCH 6: R2O — parallel output pass + fused RMSNorm/gate ----
__global__ void __launch_bounds__(256) r2o_kernel(
    const float* __restrict__ Q, const float* __restrict__ V,
    const float* __restrict__ Ai, const float* __restrict__ Sprev,
    const float* __restrict__ gate, const float* __restrict__ rms_w,
    __nv_bfloat16* __restrict__ Of)
{
    extern __shared__ float sm2[];
    float* AT = sm2;
    float* BV = sm2 + 64 * 68;
    float* BS = sm2 + 2 * 64 * 68;
    float* QT = sm2 + 3 * 64 * 68;
    int tid = threadIdx.x;
    int cb = blockIdx.x;
    int n = cb >> 5, bh = cb & 31;
    int b = bh >> 4, h = bh & 15;
    long g0 = ((long)bh * Tt + n * 64) * 64;
    long gc = (long)cb * 4096;
    int r0 = (tid >> 4) * 4, c0 = (tid & 15) * 4;

    for (int i = tid; i < 4096; i += 256) {
        int row = i >> 6, col = i & 63;
        AT[col * 68 + row] = Ai[gc + i];
        QT[col * 68 + row] = Q[g0 + i];
        BV[row * 68 + col] = V[g0 + i];
        BS[row * 68 + col] = Sprev[gc + i];
    }
    __syncthreads();

    float o[4][4];
    #pragma unroll
    for (int i = 0; i < 4; i++)
        #pragma unroll
        for (int j = 0; j < 4; j++) o[i][j] = 0.f;

    for (int kk = 0; kk < 64; kk++) {
        float4 bv = *(const float4*)&BV[kk * 68 + c0];
        float4 bs = *(const float4*)&BS[kk * 68 + c0];
        #pragma unroll
        for (int i = 0; i < 4; i++) {
            float av = (kk <= r0 + i) ? AT[kk * 68 + r0 + i] : 0.f;
            float qv = QT[kk * 68 + r0 + i];
            o[i][0] += av * bv.x + qv * bs.x;
            o[i][1] += av * bv.y + qv * bs.y;
            o[i][2] += av * bv.z + qv * bs.z;
            o[i][3] += av * bv.w + qv * bs.w;
        }
    }

    #pragma unroll
    for (int i = 0; i < 4; i++) {
        float s = o[i][0] * o[i][0] + o[i][1] * o[i][1]
                + o[i][2] * o[i][2] + o[i][3] * o[i][3];
        s += __shfl_xor_sync(0xffffffffu, s, 1);
        s += __shfl_xor_sync(0xffffffffu, s, 2);
        s += __shfl_xor_sync(0xffffffffu, s, 4);
        s += __shfl_xor_sync(0xffffffffu, s, 8);
        int tg = n * 64 + r0 + i;
        float gv = gate[((size_t)b * Tt + tg) * 16 + h];
        float sc = rsqrtf(s * (1.0f / 64.f) + 1e-6f) * gv;
        size_t m = (size_t)b * Tt + tg;
        #pragma unroll
        for (int j = 0; j < 4; j++) {
            int e = c0 + j;
            float val = o[i][j] * sc * rms_w[h * 64 + e];
            bf16_split_store(Of, (m * 32 + h * 2 + (e >> 5)) * 64 + (e & 31), val);
        }
    }
}

extern "C" void kernel_launch(void* const* d_in, const int* in_sizes, int n_in,
                              void* d_out, int out_size)
{
    const float* x   = (const float*)d_in[0];
    const float* wqc = (const float*)d_in[1];  const float* bqc = (const float*)d_in[2];
    const float* wkc = (const float*)d_in[3];  const float* bkc = (const float*)d_in[4];
    const float* wvc = (const float*)d_in[5];  const float* bvc = (const float*)d_in[6];
    const float* Wq  = (const float*)d_in[7];  const float* bq  = (const float*)d_in[8];
    const float* Wk  = (const float*)d_in[9];  const float* bk  = (const float*)d_in[10];
    const float* Wv  = (const float*)d_in[11]; const float* bv  = (const float*)d_in[12];
    const float* Wad = (const float*)d_in[13]; const float* bad = (const float*)d_in[14];
    const float* Wau = (const float*)d_in[15]; const float* bau = (const float*)d_in[16];
    const float* Wbe = (const float*)d_in[17]; const float* bbe = (const float*)d_in[18];
    const float* rmsw= (const float*)d_in[19];
    const float* Wgd = (const float*)d_in[20]; const float* bgd = (const float*)d_in[21];
    const float* Wgu = (const float*)d_in[22]; const float* bgu = (const float*)d_in[23];
    const float* Wo  = (const float*)d_in[24]; const float* bo  = (const float*)d_in[25];
    float* out = (float*)d_out;

    float* base = nullptr;
    cudaGetSymbolAddress((void**)&base, g_scratch);
    __nv_bfloat16* xq2 = (__nv_bfloat16*)(base + 0 * BLK);
    __nv_bfloat16* xk2 = (__nv_bfloat16*)(base + 1 * BLK);
    __nv_bfloat16* xv2 = (__nv_bfloat16*)(base + 2 * BLK);
    float* Qp = base + 3 * BLK;  float* Kp = base + 4 * BLK;  float* Vp = base + 5 * BLK;
    float* al = base + 6 * BLK;
    __nv_bfloat16* Of2 = (__nv_bfloat16*)(base + 8 * BLK);
    float* Ap = base + 9 * BLK;  float* Wp = base + 10 * BLK; float* T1p= base + 11 * BLK;
    float* Ktp= base + 12 * BLK;
    __nv_bfloat16* Wc = (__nv_bfloat16*)(base + 13 * BLK);
    float* Sprev = base + 14 * BLK;
    float* t1 = base + 7 * BLK;  float* t2 = t1 + 262144;
    float* be = t2 + 262144;     float* ga = be + 65536;      float* lp = ga + 65536;

    cudaFuncSetAttribute(r1_kernel, cudaFuncAttributeMaxDynamicSharedMemorySize, R1_SMEM);
    cudaFuncSetAttribute(r2s_kernel, cudaFuncAttributeMaxDynamicSharedMemorySize, R2S_SMEM);
    cudaFuncSetAttribute(r2o_kernel, cudaFuncAttributeMaxDynamicSharedMemorySize, R2O_SMEM);
    cudaFuncSetAttribute(gemm_big<0>, cudaFuncAttributeMaxDynamicSharedMemorySize, GEMM_SMEM);
    cudaFuncSetAttribute(gemm_big<1>, cudaFuncAttributeMaxDynamicSharedMemorySize, GEMM_SMEM);

    prep_kernel<<<65536, 256>>>(x, wqc, bqc, wkc, bkc, wvc, bvc,
                                Wq, Wk, Wv, Wo, xq2, xk2, xv2, Wc);
    gates1_kernel<<<768, 256>>>(x, Wad, bad, Wgd, bgd, Wbe, bbe, t1, t2, be);
    alphagate_kernel<<<1280, 256>>>(t1, Wau, bau, al, t2, Wgu, bgu, ga);

    gemm_big<1><<<dim3(8, 32, 3), 256, GEMM_SMEM>>>(xq2, xk2, xv2, Wc,
                                                    bq, bk, bv, Qp, Kp, Vp);

    r1_kernel<<<1024, 256, R1_SMEM>>>(Qp, Kp, Vp, al, be, Ap, Wp, T1p, Ktp, lp);
    r2s_kernel<<<32, 512, R2S_SMEM>>>(Wp, T1p, Ktp, lp, Sprev);
    r2o_kernel<<<1024, 256, R2O_SMEM>>>(Qp, Vp, Ap, Sprev, ga, rmsw, Of2);

    gemm_big<0><<<dim3(8, 32, 1), 256, GEMM_SMEM>>>(Of2, Of2, Of2, Wc,
                                                    bo, bo, bo, out, out, out);
}

// round 16
// speedup vs baseline: 1.2106x; 1.2106x over previous
#include <cuda_runtime.h>
#include <cuda_bf16.h>
#include <math.h>

static constexpr int Bb = 2, Tt = 2048, Dm = 1024, Hh = 16, Cc = 64;
static constexpr int BT  = Bb * Tt;
static constexpr int NC  = Tt / Cc;
static constexpr long BLK = (long)BT * Dm;

__device__ __align__(256) float g_scratch[18 * 4194304 + 2 * 262144 + 3 * 65536];

static constexpr int R1_SMEM  = (5 * 4160 + 192) * 4;   // 83968 B
static constexpr int GEMM_SMEM = 65536;
static constexpr int R2O_SMEM = 4 * 64 * 68 * 4;        // 69632 B
static constexpr int R2S_SMEM = (3 * 576 + 2 * 4160) * 4; // 40192 B

__device__ __forceinline__ unsigned smem_u32(const void* p) {
    return (unsigned)__cvta_generic_to_shared(p);
}
__device__ __forceinline__ void cp16(unsigned dst, const void* src) {
    asm volatile("cp.async.cg.shared.global [%0], [%1], 16;" :: "r"(dst), "l"(src));
}
__device__ __forceinline__ void cp_commit() {
    asm volatile("cp.async.commit_group;" ::: "memory");
}
__device__ __forceinline__ void cp_wait0() {
    asm volatile("cp.async.wait_group 0;" ::: "memory");
}
__device__ __forceinline__ void ldsm4(unsigned* r, unsigned addr) {
    asm volatile("ldmatrix.sync.aligned.m8n8.x4.shared.b16 {%0,%1,%2,%3},[%4];"
        : "=r"(r[0]), "=r"(r[1]), "=r"(r[2]), "=r"(r[3]) : "r"(addr));
}
__device__ __forceinline__ void mma_bf16(float* d, const unsigned* a, unsigned b0, unsigned b1) {
    asm volatile("mma.sync.aligned.m16n8k16.row.col.f32.bf16.bf16.f32 "
        "{%0,%1,%2,%3},{%4,%5,%6,%7},{%8,%9},{%0,%1,%2,%3};"
        : "+f"(d[0]), "+f"(d[1]), "+f"(d[2]), "+f"(d[3])
        : "r"(a[0]), "r"(a[1]), "r"(a[2]), "r"(a[3]), "r"(b0), "r"(b1));
}
__device__ __forceinline__ void bf16_split_store(__nv_bfloat16* dst, size_t idx, float v) {
    __nv_bfloat16 h = __float2bfloat16(v);
    float lo = v - __bfloat162float(h);
    dst[idx] = h;
    dst[idx + 32] = __float2bfloat16(lo);
}

// ---- LAUNCH 0: conv+SiLU + weight convert ----
__global__ void __launch_bounds__(256) prep_kernel(
    const float* __restrict__ x,
    const float* __restrict__ wq, const float* __restrict__ bq,
    const float* __restrict__ wk, const float* __restrict__ bk,
    const float* __restrict__ wv, const float* __restrict__ bv,
    const float* __restrict__ Wq, const float* __restrict__ Wk,
    const float* __restrict__ Wv, const float* __restrict__ Wo,
    __nv_bfloat16* __restrict__ xq, __nv_bfloat16* __restrict__ xk,
    __nv_bfloat16* __restrict__ xv, __nv_bfloat16* __restrict__ Wc)
{
    if (blockIdx.x < 49152) {
        long idx = (long)blockIdx.x * 256 + threadIdx.x;
        int d = (int)(idx & (Dm - 1));
        int t = (int)((idx >> 10) & (Tt - 1));
        int b = (int)((idx >> 21) & 1);
        int s = (int)(idx >> 22);
        const float* w  = (s == 0) ? wq : (s == 1) ? wk : wv;
        const float* bi = (s == 0) ? bq : (s == 1) ? bk : bv;
        __nv_bfloat16* o = (s == 0) ? xq : (s == 1) ? xk : xv;
        float acc = bi[d];
        #pragma unroll
        for (int j = 0; j < 4; j++) {
            int tt = t - 3 + j;
            if (tt >= 0) acc += x[((long)b * Tt + tt) * Dm + d] * w[d * 4 + j];
        }
        float sg = 1.0f / (1.0f + __expf(-acc));
        size_t m = (size_t)b * Tt + t;
        bf16_split_store(o, (m * 32 + (d >> 5)) * 64 + (d & 31), acc * sg);
    } else {
        long idx = (long)(blockIdx.x - 49152) * 256 + threadIdx.x;
        int mid = (int)(idx >> 20);
        int r = (int)((idx >> 10) & 1023), k = (int)(idx & 1023);
        const float* src = (mid == 0) ? Wq : (mid == 1) ? Wk : (mid == 2) ? Wv : Wo;
        float a = src[(size_t)r * 1024 + k];
        bf16_split_store(Wc + (size_t)mid * 2097152,
                         ((size_t)r * 32 + (k >> 5)) * 64 + (k & 31), a);
    }
}

// ---- LAUNCH 1: gate down-projections ----
__global__ void __launch_bounds__(256) gates1_kernel(
    const float* __restrict__ x,
    const float* __restrict__ Wad, const float* __restrict__ bad,
    const float* __restrict__ Wgd, const float* __restrict__ bgd,
    const float* __restrict__ Wbe, const float* __restrict__ bbe,
    float* __restrict__ t1, float* __restrict__ t2, float* __restrict__ be)
{
    __shared__ float As[16][65];
    __shared__ float Ws[64][65];
    int bid = blockIdx.x, tid = threadIdx.x;
    int sel = bid >> 8;
    int m0 = (bid & 255) * 16;
    if (sel < 2) {
        const float* W  = sel ? Wgd : Wad;
        const float* bi = sel ? bgd : bad;
        float* outp     = sel ? t2 : t1;
        int col = tid & 63, rg = tid >> 6;
        float acc[4] = {0.f, 0.f, 0.f, 0.f};
        for (int k0 = 0; k0 < 1024; k0 += 64) {
            for (int i = tid; i < 1024; i += 256)
                As[i >> 6][i & 63] = x[(size_t)(m0 + (i >> 6)) * 1024 + k0 + (i & 63)];
            for (int i = tid; i < 4096; i += 256)
                Ws[i >> 6][i & 63] = W[(size_t)(i >> 6) * 1024 + k0 + (i & 63)];
            __syncthreads();
            for (int kk = 0; kk < 64; kk++) {
                float w = Ws[col][kk];
                acc[0] += As[rg][kk] * w;      acc[1] += As[rg + 4][kk] * w;
                acc[2] += As[rg + 8][kk] * w;  acc[3] += As[rg + 12][kk] * w;
            }
            __syncthreads();
        }
        #pragma unroll
        for (int i = 0; i < 4; i++) {
            float v = acc[i] + bi[col];
            v = v / (1.0f + __expf(-v));
            outp[(size_t)(m0 + rg + i * 4) * 64 + col] = v;
        }
    } else {
        int col = tid & 15, rg = tid >> 4;
        float acc = 0.f;
        for (int k0 = 0; k0 < 1024; k0 += 64) {
            for (int i = tid; i < 1024; i += 256)
                As[i >> 6][i & 63] = x[(size_t)(m0 + (i >> 6)) * 1024 + k0 + (i & 63)];
            for (int i = tid; i < 1024; i += 256)
                Ws[i >> 6][i & 63] = Wbe[(size_t)(i >> 6) * 1024 + k0 + (i & 63)];
            __syncthreads();
            for (int kk = 0; kk < 64; kk++) acc += As[rg][kk] * Ws[col][kk];
            __syncthreads();
        }
        float v = acc + bbe[col];
        float s = 1.0f / (1.0f + __expf(-v));
        be[(size_t)(m0 + rg) * 16 + col] = fminf(s, 1.0f);
    }
}

// ---- LAUNCH 2: merged alpha up-proj + output gate up-proj ----
__global__ void __launch_bounds__(256) alphagate_kernel(
    const float* __restrict__ t1, const float* __restrict__ Wau,
    const float* __restrict__ bau, float* __restrict__ al,
    const float* __restrict__ t2, const float* __restrict__ Wgu,
    const float* __restrict__ bgu, float* __restrict__ ga)
{
    int tid = threadIdx.x;
    if (blockIdx.x < 1024) {
        __shared__ float As[16][68];
        __shared__ float Ws[16][68];
        int m0 = (blockIdx.x >> 4) * 64, n0 = (blockIdx.x & 15) * 64;
        int lr = tid >> 2, lk = (tid & 3) * 4;
        int r0 = (tid >> 4) * 4, c0 = (tid & 15) * 4;
        float acc[4][4];
        #pragma unroll
        for (int i = 0; i < 4; i++)
            #pragma unroll
            for (int j = 0; j < 4; j++) acc[i][j] = 0.f;
        for (int k0 = 0; k0 < 64; k0 += 16) {
            float4 av = *(const float4*)&t1[(size_t)(m0 + lr) * 64 + k0 + lk];
            float4 wv = *(const float4*)&Wau[(size_t)(n0 + lr) * 64 + k0 + lk];
            As[lk + 0][lr] = av.x; As[lk + 1][lr] = av.y; As[lk + 2][lr] = av.z; As[lk + 3][lr] = av.w;
            Ws[lk + 0][lr] = wv.x; Ws[lk + 1][lr] = wv.y; Ws[lk + 2][lr] = wv.z; Ws[lk + 3][lr] = wv.w;
            __syncthreads();
            #pragma unroll
            for (int kk = 0; kk < 16; kk++) {
                float4 a4 = *(const float4*)&As[kk][r0];
                float4 w4 = *(const float4*)&Ws[kk][c0];
                float aa[4] = {a4.x, a4.y, a4.z, a4.w};
                float ww[4] = {w4.x, w4.y, w4.z, w4.w};
                #pragma unroll
                for (int i = 0; i < 4; i++)
                    #pragma unroll
                    for (int j = 0; j < 4; j++) acc[i][j] += aa[i] * ww[j];
            }
            __syncthreads();
        }
        #pragma unroll
        for (int i = 0; i < 4; i++) {
            int m = m0 + r0 + i;
            #pragma unroll
            for (int j = 0; j < 4; j++) {
                int nn = n0 + c0 + j;
                float v = acc[i][j] + bau[nn];
                float s = 1.0f / (1.0f + __expf(-v));
                v = fminf(fmaxf(s, 0.1f), 1.0f);
                int b = m >> 11, t = m & 2047;
                int h = nn >> 6, d = nn & 63;
                al[(((size_t)b * Hh + h) * Tt + t) * 64 + d] = v;
            }
        }
    } else {
        __shared__ float As2[16][65];
        __shared__ float Ws2[16][65];
        int m0 = (blockIdx.x - 1024) * 16;
        int col = tid & 15, rg = tid >> 4;
        float acc = 0.f;
        for (int i = tid; i < 1024; i += 256)
            As2[i >> 6][i & 63] = t2[(size_t)(m0 + (i >> 6)) * 64 + (i & 63)];
        for (int i = tid; i < 1024; i += 256)
            Ws2[i >> 6][i & 63] = Wgu[(size_t)(i >> 6) * 64 + (i & 63)];
        __syncthreads();
        for (int kk = 0; kk < 64; kk++) acc += As2[rg][kk] * Ws2[col][kk];
        float v = acc + bgu[col];
        float s = 1.0f / (1.0f + __expf(-v));
        ga[(size_t)(m0 + rg) * 16 + col] = fminf(s, 1.0f);
    }
}

// ---- LAUNCH 3: big tensor-core GEMM, 2 CTAs/SM ----
template<int MODE>
__global__ void __launch_bounds__(256, 2) gemm_big(
    const __nv_bfloat16* __restrict__ A0, const __nv_bfloat16* __restrict__ A1,
    const __nv_bfloat16* __restrict__ A2, const __nv_bfloat16* __restrict__ Wbase,
    const float* __restrict__ b0, const float* __restrict__ b1,
    const float* __restrict__ b2,
    float* __restrict__ C0, float* __restrict__ C1, float* __restrict__ C2)
{
    extern __shared__ __align__(16) char dynsm[];
    unsigned sbase = smem_u32(dynsm);
    int z = MODE ? blockIdx.z : 3;
    const __nv_bfloat16* A = (z == 0 || z == 3) ? A0 : (z == 1) ? A1 : A2;
    const __nv_bfloat16* W2 = Wbase + (size_t)z * 2097152;
    const float* bias = (z == 0 || z == 3) ? b0 : (z == 1) ? b1 : b2;
    float* C = (z == 0 || z == 3) ? C0 : (z == 1) ? C1 : C2;

    int tid = threadIdx.x;
    int lane = tid & 31, warp = tid >> 5;
    int wn = warp & 1, wm = warp >> 1;
    int m0 = blockIdx.y * 128, n0 = blockIdx.x * 128;
    const int NKC = 32;

    float acc[2][8][4];
    #pragma unroll
    for (int a = 0; a < 2; a++)
        #pragma unroll
        for (int b = 0; b < 8; b++)
            #pragma unroll
            for (int c = 0; c < 4; c++) acc[a][b][c] = 0.f;

    auto load_stage = [&](int s, int c) {
        unsigned abase = sbase + s * 32768;
        unsigned wbase = abase + 16384;
        #pragma unroll
        for (int i = tid; i < 1024; i += 256) {
            int row = i >> 3, q = i & 7;
            unsigned off = row * 128 + ((q ^ (row & 7)) << 4);
            cp16(abase + off, A + ((size_t)(m0 + row) * NKC + c) * 64 + q * 8);
            cp16(wbase + off, W2 + ((size_t)(n0 + row) * NKC + c) * 64 + q * 8);
        }
        cp_commit();
    };

    load_stage(0, 0);
    int cur = 0;
    for (int c = 0; c < NKC; c++) {
        cp_wait0();
        __syncthreads();
        if (c + 1 < NKC) load_stage(cur ^ 1, c + 1);
        unsigned as = sbase + cur * 32768;
        unsigned ws = as + 16384;
        #pragma unroll
        for (int kk = 0; kk < 2; kk++) {
            unsigned a_h[2][4], a_l[2][4];
            #pragma unroll
            for (int mt = 0; mt < 2; mt++) {
                int row = wm * 32 + mt * 16 + (lane & 15);
                int chB = kk * 2 + (lane >> 4);
                ldsm4(a_h[mt], as + row * 128 + ((chB ^ (row & 7)) << 4));
                ldsm4(a_l[mt], as + row * 128 + (((chB + 4) ^ (row & 7)) << 4));
            }
            unsigned b_h[4][4], b_l[4][4];
            #pragma unroll
            for (int nt4 = 0; nt4 < 4; nt4++) {
                int row = wn * 64 + nt4 * 16 + (lane & 15);
                int chB = kk * 2 + (lane >> 4);
                ldsm4(b_h[nt4], ws + row * 128 + ((chB ^ (row & 7)) << 4));
                ldsm4(b_l[nt4], ws + row * 128 + (((chB + 4) ^ (row & 7)) << 4));
            }
            #pragma unroll
            for (int mt = 0; mt < 2; mt++)
                #pragma unroll
                for (int nt = 0; nt < 8; nt++) {
                    int q = nt >> 1, h = nt & 1;
                    mma_bf16(acc[mt][nt], a_h[mt], b_h[q][h], b_h[q][h + 2]);
                    mma_bf16(acc[mt][nt], a_h[mt], b_l[q][h], b_l[q][h + 2]);
                    mma_bf16(acc[mt][nt], a_l[mt], b_h[q][h], b_h[q][h + 2]);
                }
        }
        cur ^= 1;
    }

    int g = lane >> 2, tc = (lane & 3) * 2;
    #pragma unroll
    for (int mt = 0; mt < 2; mt++) {
        #pragma unroll
        for (int nt = 0; nt < 8; nt++)
            #pragma unroll
            for (int q = 0; q < 2; q++) {
                float bv = bias[n0 + wn * 64 + nt * 8 + tc + q];
                acc[mt][nt][q] += bv;
                acc[mt][nt][2 + q] += bv;
            }
        if (MODE && z < 2) {
            #pragma unroll
            for (int p = 0; p < 2; p++) {
                float s = 0.f;
                #pragma unroll
                for (int nt = 0; nt < 8; nt++)
                    #pragma unroll
                    for (int q = 0; q < 2; q++) {
                        float v = acc[mt][nt][p * 2 + q];
                        s += v * v;
                    }
                s += __shfl_xor_sync(0xffffffffu, s, 1);
                s += __shfl_xor_sync(0xffffffffu, s, 2);
                float inv = rsqrtf(fmaxf(s, 1e-6f));
                #pragma unroll
                for (int nt = 0; nt < 8; nt++)
                    #pragma unroll
                    for (int q = 0; q < 2; q++)
                        acc[mt][nt][p * 2 + q] *= inv;
            }
        }
        #pragma unroll
        for (int nt = 0; nt < 8; nt++)
            #pragma unroll
            for (int p = 0; p < 2; p++)
                #pragma unroll
                for (int q = 0; q < 2; q++) {
                    int row = m0 + wm * 32 + mt * 16 + g + p * 8;
                    int col = n0 + wn * 64 + nt * 8 + tc + q;
                    float v = acc[mt][nt][p * 2 + q];
                    if (MODE) {
                        int b = row >> 11, t = row & 2047;
                        int h = col >> 6, d = col & 63;
                        C[(((size_t)b * Hh + h) * Tt + t) * 64 + d] = v;
                    } else {
                        C[(size_t)row * 1024 + col] = v;
                    }
                }
    }
}

// ---- LAUNCH 4: R1 (liveness-overlapped smem) ----
__global__ void __launch_bounds__(256) r1_kernel(
    const float* __restrict__ Q, const float* __restrict__ K,
    const float* __restrict__ V, const float* __restrict__ AL,
    const float* __restrict__ BETA,
    float* __restrict__ Ao, float* __restrict__ Wo_, float* __restrict__ T1o,
    float* __restrict__ Kto, float* __restrict__ lamo)
{
    extern __shared__ float sm[];
    float* cl = sm;
    float* pA = sm + 4160;
    float* Us = sm;
    float* pB = sm + 2 * 4160;
    float* pC = sm + 3 * 4160;
    float* Ms = sm + 4 * 4160;
    float* bs = sm + 5 * 4160;
    float* Em = bs + 64;
    float* E63 = Em + 64;
    int tid = threadIdx.x;
    int cb = blockIdx.x;
    int n = cb >> 5, bh = cb & 31;
    int b = bh >> 4, h = bh & 15;
    long g0 = ((long)bh * Tt + n * 64) * 64;

    for (int i = tid; i < 4096; i += 256) {
        int t = i >> 6, d = i & 63;
        pA[t * 65 + d] = Q[g0 + i];
        pB[t * 65 + d] = K[g0 + i];
        Ms[t * 65 + d] = AL[g0 + i];
    }
    if (tid < 64) bs[tid] = BETA[((long)b * Tt + n * 64 + tid) * 16 + h];
    __syncthreads();

    if (tid < 64) {
        float c = 0.f;
        for (int t = 0; t < 64; t++) {
            c += __logf(fmaxf(Ms[t * 65 + tid], 1e-7f));
            cl[t * 65 + tid] = c;
        }
        float m = cl[31 * 65 + tid];
        Em[tid]  = __expf(m);
        E63[tid] = __expf(cl[63 * 65 + tid] - m);
    }
    __syncthreads();
    for (int i = tid; i < 4096; i += 256) {
        int t = i >> 6, d = i & 63;
        float m  = cl[31 * 65 + d];
        float e  = __expf(cl[t * 65 + d] - m);
        float ei = __expf(m - cl[t * 65 + d]);
        float q = pA[t * 65 + d], k = pB[t * 65 + d];
        pA[t * 65 + d] = q * e;
        pB[t * 65 + d] = k * e;
        pC[t * 65 + d] = k * bs[t] * ei;
    }
    __syncthreads();

    for (int p = tid; p < 2080; p += 256) {
        int i = (int)((sqrtf(8.f * p + 1.f) - 1.f) * 0.5f);
        while ((i + 1) * (i + 2) / 2 <= p) ++i;
        while (i * (i + 1) / 2 > p) --i;
        int j = p - ((i * (i + 1)) >> 1);
        float accA = 0.f, accM = 0.f;
        const float* ai = pA + i * 65;
        const float* bi = pB + i * 65;
        const float* cj = pC + j * 65;
        #pragma unroll 16
        for (int d = 0; d < 64; d++) {
            float c = cj[d];
            accA += ai[d] * c;
            accM += bi[d] * c;
        }
        Ao[(long)cb * 4096 + i * 64 + j] = accA;
        Ms[i * 65 + j] = accM;
    }
    __syncthreads();

    if (tid < 128) {
        int c = tid;
        int d = c & 63;
        for (int t = 0; t < 64; t++) {
            float acc;
            if (c < 64) acc = V[g0 + t * 64 + d];
            else        acc = pB[t * 65 + d];
            for (int s = 0; s < t; s++) acc -= Ms[t * 65 + s] * Us[s * 128 + c];
            Us[t * 128 + c] = acc;
        }
    }
    __syncthreads();

    for (int i = tid; i < 4096; i += 256) {
        int t = i >> 6, e = i & 63;
        T1o[(long)cb * 4096 + i] = Us[t * 128 + e];
        Wo_[(long)cb * 4096 + i] = Us[t * 128 + 64 + e] * Em[e];
        Kto[(long)cb * 4096 + i] = pC[t * 65 + e] * E63[e];
    }
    if (tid < 64) lamo[(long)cb * 64 + tid] = Em[tid] * E63[tid];
}

// ---- LAUNCH 5: R2S — 256 blocks (bh x 8-col slice), 3 syncs/chunk ----
__global__ void __launch_bounds__(256) r2s_kernel(
    const float* __restrict__ Wi, const float* __restrict__ T1i,
    const float* __restrict__ Kti, const float* __restrict__ lami,
    float* __restrict__ Sprev)
{
    extern __shared__ float smS[];
    float* S  = smS;                // 64*9
    float* U  = smS + 576;          // 64*9
    float* R  = smS + 1152;         // 64*9
    float* LW = smS + 1728;         // 64*65
    float* LK = smS + 1728 + 4160;  // 64*65
    int tid = threadIdx.x;
    int bh = blockIdx.x >> 3, eb = blockIdx.x & 7;
    int e0 = eb * 8;
    int r = tid & 63, ch = tid >> 6, c0 = ch * 2;
    for (int i = tid; i < 576; i += 256) S[i] = 0.f;

    // chunk-0 checkpoint is identically zero: write constants (no smem dep)
    {
        long gc0 = (long)bh * 4096;
        Sprev[gc0 + r * 64 + e0 + c0]     = 0.f;
        Sprev[gc0 + r * 64 + e0 + c0 + 1] = 0.f;
    }

    float wR[16], tR[2], kR[16], lamR;
    {
        long gc = (long)bh * 4096;
        #pragma unroll
        for (int m = 0; m < 16; m++) wR[m] = Wi[gc + tid + m * 256];
        #pragma unroll
        for (int m = 0; m < 16; m++) kR[m] = Kti[gc + tid + m * 256];
        tR[0] = T1i[gc + r * 64 + e0 + c0];
        tR[1] = T1i[gc + r * 64 + e0 + c0 + 1];
        lamR = lami[(long)bh * 64 + r];
    }

    for (int n = 0; n < NC; n++) {
        __syncthreads();   // prior chunk's LK/U/S reads done; S init visible (n=0)
        #pragma unroll
        for (int m = 0; m < 16; m++) { int i = tid + m * 256; LW[(i >> 6) * 65 + (i & 63)] = wR[m]; }
        #pragma unroll
        for (int m = 0; m < 16; m++) { int i = tid + m * 256; LK[(i >> 6) * 65 + (i & 63)] = kR[m]; }
        R[r * 9 + c0]     = tR[0];
        R[r * 9 + c0 + 1] = tR[1];
        __syncthreads();
        // prefetch next chunk into registers during compute
        float lamCur = lamR;
        if (n + 1 < NC) {
            long gc2 = ((long)(n + 1) * 32 + bh) * 4096;
            #pragma unroll
            for (int m = 0; m < 16; m++) wR[m] = Wi[gc2 + tid + m * 256];
            #pragma unroll
            for (int m = 0; m < 16; m++) kR[m] = Kti[gc2 + tid + m * 256];
            tR[0] = T1i[gc2 + r * 64 + e0 + c0];
            tR[1] = T1i[gc2 + r * 64 + e0 + c0 + 1];
            lamR = lami[((long)(n + 1) * 32 + bh) * 64 + r];
        }
        // U = T1 - W @ S
        {
            float u0 = R[r * 9 + c0], u1 = R[r * 9 + c0 + 1];
            for (int kk = 0; kk < 64; kk++) {
                float w = LW[r * 65 + kk];
                u0 -= w * S[kk * 9 + c0];
                u1 -= w * S[kk * 9 + c0 + 1];
            }
            U[r * 9 + c0] = u0;
            U[r * 9 + c0 + 1] = u1;
        }
        __syncthreads();
        // S = diag(lam)*S + Kt^T @ U ; checkpoint next chunk from registers
        {
            float s0 = lamCur * S[r * 9 + c0], s1 = lamCur * S[r * 9 + c0 + 1];
            for (int kk = 0; kk < 64; kk++) {
                float kv = LK[kk * 65 + r];
                s0 += kv * U[kk * 9 + c0];
                s1 += kv * U[kk * 9 + c0 + 1];
            }
            S[r * 9 + c0] = s0;
            S[r * 9 + c0 + 1] = s1;
            if (n + 1 < NC) {
                long gc2 = ((long)(n + 1) * 32 + bh) * 4096;
                Sprev[gc2 + r * 64 + e0 + c0]     = s0;
                Sprev[gc2 + r * 64 + e0 + c0 + 1] = s1;
            }
        }
    }
}

// ---- LAUNCH 6: R2O — parallel output pass + fused RMSNorm/gate ----
__global__ void __launch_bounds__(256) r2o_kernel(
    const float* __restrict__ Q, const float* __restrict__ V,
    const float* __restrict__ Ai, const float* __restrict__ Sprev,
    const float* __restrict__ gate, const float* __restrict__ rms_w,
    __nv_bfloat16* __restrict__ Of)
{
    extern __shared__ float sm2[];
    float* AT = sm2;
    float* BV = sm2 + 64 * 68;
    float* BS = sm2 + 2 * 64 * 68;
    float* QT = sm2 + 3 * 64 * 68;
    int tid = threadIdx.x;
    int cb = blockIdx.x;
    int n = cb >> 5, bh = cb & 31;
    int b = bh >> 4, h = bh & 15;
    long g0 = ((long)bh * Tt + n * 64) * 64;
    long gc = (long)cb * 4096;
    int r0 = (tid >> 4) * 4, c0 = (tid & 15) * 4;

    for (int i = tid; i < 4096; i += 256) {
        int row = i >> 6, col = i & 63;
        AT[col * 68 + row] = Ai[gc + i];
        QT[col * 68 + row] = Q[g0 + i];
        BV[row * 68 + col] = V[g0 + i];
        BS[row * 68 + col] = Sprev[gc + i];
    }
    __syncthreads();

    float o[4][4];
    #pragma unroll
    for (int i = 0; i < 4; i++)
        #pragma unroll
        for (int j = 0; j < 4; j++) o[i][j] = 0.f;

    for (int kk = 0; kk < 64; kk++) {
        float4 bv = *(const float4*)&BV[kk * 68 + c0];
        float4 bs = *(const float4*)&BS[kk * 68 + c0];
        #pragma unroll
        for (int i = 0; i < 4; i++) {
            float av = (kk <= r0 + i) ? AT[kk * 68 + r0 + i] : 0.f;
            float qv = QT[kk * 68 + r0 + i];
            o[i][0] += av * bv.x + qv * bs.x;
            o[i][1] += av * bv.y + qv * bs.y;
            o[i][2] += av * bv.z + qv * bs.z;
            o[i][3] += av * bv.w + qv * bs.w;
        }
    }

    #pragma unroll
    for (int i = 0; i < 4; i++) {
        float s = o[i][0] * o[i][0] + o[i][1] * o[i][1]
                + o[i][2] * o[i][2] + o[i][3] * o[i][3];
        s += __shfl_xor_sync(0xffffffffu, s, 1);
        s += __shfl_xor_sync(0xffffffffu, s, 2);
        s += __shfl_xor_sync(0xffffffffu, s, 4);
        s += __shfl_xor_sync(0xffffffffu, s, 8);
        int tg = n * 64 + r0 + i;
        float gv = gate[((size_t)b * Tt + tg) * 16 + h];
        float sc = rsqrtf(s * (1.0f / 64.f) + 1e-6f) * gv;
        size_t m = (size_t)b * Tt + tg;
        #pragma unroll
        for (int j = 0; j < 4; j++) {
            int e = c0 + j;
            float val = o[i][j] * sc * rms_w[h * 64 + e];
            bf16_split_store(Of, (m * 32 + h * 2 + (e >> 5)) * 64 + (e & 31), val);
        }
    }
}

extern "C" void kernel_launch(void* const* d_in, const int* in_sizes, int n_in,
                              void* d_out, int out_size)
{
    const float* x   = (const float*)d_in[0];
    const float* wqc = (const float*)d_in[1];  const float* bqc = (const float*)d_in[2];
    const float* wkc = (const float*)d_in[3];  const float* bkc = (const float*)d_in[4];
    const float* wvc = (const float*)d_in[5];  const float* bvc = (const float*)d_in[6];
    const float* Wq  = (const float*)d_in[7];  const float* bq  = (const float*)d_in[8];
    const float* Wk  = (const float*)d_in[9];  const float* bk  = (const float*)d_in[10];
    const float* Wv  = (const float*)d_in[11]; const float* bv  = (const float*)d_in[12];
    const float* Wad = (const float*)d_in[13]; const float* bad = (const float*)d_in[14];
    const float* Wau = (const float*)d_in[15]; const float* bau = (const float*)d_in[16];
    const float* Wbe = (const float*)d_in[17]; const float* bbe = (const float*)d_in[18];
    const float* rmsw= (const float*)d_in[19];
    const float* Wgd = (const float*)d_in[20]; const float* bgd = (const float*)d_in[21];
    const float* Wgu = (const float*)d_in[22]; const float* bgu = (const float*)d_in[23];
    const float* Wo  = (const float*)d_in[24]; const float* bo  = (const float*)d_in[25];
    float* out = (float*)d_out;

    float* base = nullptr;
    cudaGetSymbolAddress((void**)&base, g_scratch);
    __nv_bfloat16* xq2 = (__nv_bfloat16*)(base + 0 * BLK);
    __nv_bfloat16* xk2 = (__nv_bfloat16*)(base + 1 * BLK);
    __nv_bfloat16* xv2 = (__nv_bfloat16*)(base + 2 * BLK);
    float* Qp = base + 3 * BLK;  float* Kp = base + 4 * BLK;  float* Vp = base + 5 * BLK;
    float* al = base + 6 * BLK;
    __nv_bfloat16* Of2 = (__nv_bfloat16*)(base + 8 * BLK);
    float* Ap = base + 9 * BLK;  float* Wp = base + 10 * BLK; float* T1p= base + 11 * BLK;
    float* Ktp= base + 12 * BLK;
    __nv_bfloat16* Wc = (__nv_bfloat16*)(base + 13 * BLK);
    float* Sprev = base + 14 * BLK;
    float* t1 = base + 7 * BLK;  float* t2 = t1 + 262144;
    float* be = t2 + 262144;     float* ga = be + 65536;      float* lp = ga + 65536;

    cudaFuncSetAttribute(r1_kernel, cudaFuncAttributeMaxDynamicSharedMemorySize, R1_SMEM);
    cudaFuncSetAttribute(r2s_kernel, cudaFuncAttributeMaxDynamicSharedMemorySize, R2S_SMEM);
    cudaFuncSetAttribute(r2o_kernel, cudaFuncAttributeMaxDynamicSharedMemorySize, R2O_SMEM);
    cudaFuncSetAttribute(gemm_big<0>, cudaFuncAttributeMaxDynamicSharedMemorySize, GEMM_SMEM);
    cudaFuncSetAttribute(gemm_big<1>, cudaFuncAttributeMaxDynamicSharedMemorySize, GEMM_SMEM);

    prep_kernel<<<65536, 256>>>(x, wqc, bqc, wkc, bkc, wvc, bvc,
                                Wq, Wk, Wv, Wo, xq2, xk2, xv2, Wc);
    gates1_kernel<<<768, 256>>>(x, Wad, bad, Wgd, bgd, Wbe, bbe, t1, t2, be);
    alphagate_kernel<<<1280, 256>>>(t1, Wau, bau, al, t2, Wgu, bgu, ga);

    gemm_big<1><<<dim3(8, 32, 3), 256, GEMM_SMEM>>>(xq2, xk2, xv2, Wc,
                                                    bq, bk, bv, Qp, Kp, Vp);

    r1_kernel<<<1024, 256, R1_SMEM>>>(Qp, Kp, Vp, al, be, Ap, Wp, T1p, Ktp, lp);
    r2s_kernel<<<256, 256, R2S_SMEM>>>(Wp, T1p, Ktp, lp, Sprev);
    r2o_kernel<<<1024, 256, R2O_SMEM>>>(Qp, Vp, Ap, Sprev, ga, rmsw, Of2);

    gemm_big<0><<<dim3(8, 32, 1), 256, GEMM_SMEM>>>(Of2, Of2, Of2, Wc,
                                                    bo, bo, bo, out, out, out);
}